// round 13
// baseline (speedup 1.0000x reference)
#include <cuda_runtime.h>
#include <cuda_bf16.h>

// WCSS: loss = mean_k [ (S2_k - ||S1_k||^2 / n_k) / (n_k * D) ]
//
// R12 post-mortem: main at DRAM floor (~26us); wcss_final (5.5us) was
// mostly scalar-load latency + an extra launch + the zero sweep. R13:
// m2red already reads every g_colsum element -> it stores 0 back in place,
// and its LAST block (threadfence + atomic counter) computes the scalar
// output and zeroes the per-class accumulators. One fewer kernel.

#define TPB   128            // threads per main block
#define CPB   (TPB * 2)      // 256 columns per block (float2/thread)
#define SEGR  128            // rows per segment
#define SLOT  2048           // g_order capacity per class
#define KMAX  16             // max classes (problem uses 10)
#define DMAX  8192           // max D (problem uses 6144)

__device__ float  g_colsum[KMAX * DMAX];  // per-class column sums
__device__ double g_S2[KMAX];             // per-class sum of squares
__device__ double g_M2[KMAX];             // per-class ||S1_k||^2
__device__ int    g_cnt[KMAX];
__device__ int    g_order[KMAX * SLOT];   // row ids, per-class slots
__device__ int    g_done;                 // m2fin completion counter

// ---------------------------------------------------------------------------
// grid = ceil(N/1024), block 1024. One label per thread. Per-warp smem
// histograms -> one global reservation atomic per (block,class) -> scatter.
__global__ void wcss_scatter(const int* __restrict__ y, int N)
{
    __shared__ int wcnt[32][KMAX];
    __shared__ int sbase[KMAX];

    const int tid  = threadIdx.x;
    const int w    = tid >> 5;
    const int lane = tid & 31;
    const int i    = blockIdx.x * 1024 + tid;

    if (lane < KMAX) wcnt[w][lane] = 0;
    __syncthreads();

    int lab = -1;
    if (i < N) {
        lab = __ldg(&y[i]) & (KMAX - 1);
        atomicAdd(&wcnt[w][lab], 1);
    }
    __syncthreads();

    // Thread k (<KMAX): exclusive prefix over warps + global reservation.
    if (tid < KMAX) {
        int acc = 0;
        #pragma unroll
        for (int w2 = 0; w2 < 32; w2++) {
            int v = wcnt[w2][tid];
            wcnt[w2][tid] = acc;
            acc += v;
        }
        sbase[tid] = atomicAdd(&g_cnt[tid], acc);
    }
    __syncthreads();
    if (lane < KMAX) wcnt[w][lane] += sbase[lane];
    __syncthreads();

    if (lab >= 0) {
        int pos = atomicAdd(&wcnt[w][lab], 1);
        if (pos < SLOT) g_order[lab * SLOT + pos] = i;
    }
}

// ---------------------------------------------------------------------------
// grid = (colChunks, KMAX, SEGS). Block (x, c, s): class c, rows
// [s*SEGR, ...) of its slot, 2 columns per thread. Register accumulators,
// flush: 2 spread float atomics per thread (colsum) + 1 double atomic (S2).
__global__ __launch_bounds__(TPB)
void wcss_main(const float* __restrict__ X, int D)
{
    const int c  = blockIdx.y;
    const int cn = min(g_cnt[c], SLOT);
    const int r0 = blockIdx.z * SEGR;
    if (r0 >= cn) return;
    const int len = min(SEGR, cn - r0);

    const int tid = threadIdx.x;

    __shared__ size_t offs[SEGR];       // byte offsets: row * D * 4
    if (tid < len)
        offs[tid] = (size_t)g_order[c * SLOT + r0 + tid] * (size_t)D * 4u;
    __syncthreads();

    const int d2 = blockIdx.x * CPB + tid * 2;
    float2 s = make_float2(0.f, 0.f);
    float2 q = make_float2(0.f, 0.f);

    if (d2 + 1 < D) {
        const char* __restrict__ bp = (const char*)X + (size_t)d2 * 4u;
        int i = 0;
        for (; i + 8 <= len; i += 8) {
            float2 x[8];
            #pragma unroll
            for (int u = 0; u < 8; u++)
                x[u] = __ldg((const float2*)(bp + offs[i + u]));
            #pragma unroll
            for (int u = 0; u < 8; u++) {
                s.x += x[u].x; q.x = fmaf(x[u].x, x[u].x, q.x);
                s.y += x[u].y; q.y = fmaf(x[u].y, x[u].y, q.y);
            }
        }
        for (; i < len; i++) {
            float2 x = __ldg((const float2*)(bp + offs[i]));
            s.x += x.x; q.x = fmaf(x.x, x.x, q.x);
            s.y += x.y; q.y = fmaf(x.y, x.y, q.y);
        }
        atomicAdd(&g_colsum[c * D + d2],     s.x);
        atomicAdd(&g_colsum[c * D + d2 + 1], s.y);
    } else if (d2 < D) {
        for (int i = 0; i < len; i++) {
            float xv = __ldg((const float*)((const char*)X + offs[i]) + d2);
            s.x += xv; q.x = fmaf(xv, xv, q.x);
        }
        atomicAdd(&g_colsum[c * D + d2], s.x);
    }

    // Block-reduce sumsq -> one double atomic.
    float qt = q.x + q.y;
    #pragma unroll
    for (int o = 16; o > 0; o >>= 1)
        qt += __shfl_down_sync(0xffffffffu, qt, o);

    __shared__ float qs[TPB / 32];
    if ((tid & 31) == 0) qs[tid >> 5] = qt;
    __syncthreads();
    if (tid == 0) {
        float qv = 0.f;
        #pragma unroll
        for (int w = 0; w < TPB / 32; w++) qv += qs[w];
        atomicAdd(&g_S2[c], (double)qv);
    }
}

// ---------------------------------------------------------------------------
// grid = (colChunks, KMAX): square + reduce colsum -> g_M2[c], zeroing
// colsum in place. The LAST block (threadfence + counter) computes the
// scalar output and resets all per-class accumulators for the next replay.
__global__ __launch_bounds__(TPB)
void wcss_m2fin(int D, int nblocks, float* __restrict__ out)
{
    const int c   = blockIdx.y;
    const int tid = threadIdx.x;
    const int d2  = blockIdx.x * CPB + tid * 2;

    float m2 = 0.f;
    if (d2 + 1 < D) {
        float vx = g_colsum[c * D + d2];
        float vy = g_colsum[c * D + d2 + 1];
        m2 = vx * vx + vy * vy;
        g_colsum[c * D + d2]     = 0.f;      // zero in place for next call
        g_colsum[c * D + d2 + 1] = 0.f;
    } else if (d2 < D) {
        float vx = g_colsum[c * D + d2];
        m2 = vx * vx;
        g_colsum[c * D + d2] = 0.f;
    }

    #pragma unroll
    for (int o = 16; o > 0; o >>= 1)
        m2 += __shfl_down_sync(0xffffffffu, m2, o);

    __shared__ float ms[TPB / 32];
    if ((tid & 31) == 0) ms[tid >> 5] = m2;
    __syncthreads();
    if (tid == 0) {
        float mv = 0.f;
        #pragma unroll
        for (int w = 0; w < TPB / 32; w++) mv += ms[w];
        atomicAdd(&g_M2[c], (double)mv);
    }

    // Last-block finalize.
    __shared__ int last_sh;
    __threadfence();                      // make this block's writes visible
    if (tid == 0)
        last_sh = (atomicAdd(&g_done, 1) == nblocks - 1);
    __syncthreads();
    if (!last_sh) return;

    if (tid < 32) {
        double lk = 0.0;
        int    present = 0;
        if (tid < KMAX) {
            int cc = min(g_cnt[tid], SLOT);        // parallel loads
            if (cc > 0) {
                double n = (double)cc;
                lk = (g_S2[tid] - g_M2[tid] / n) / (n * (double)D);
                present = 1;
            }
            g_S2[tid] = 0.0;                       // reset for next replay
            g_M2[tid] = 0.0;
            g_cnt[tid] = 0;
        }
        #pragma unroll
        for (int o = 8; o > 0; o >>= 1) {
            lk      += __shfl_down_sync(0xffffffffu, lk, o);
            present += __shfl_down_sync(0xffffffffu, present, o);
        }
        if (tid == 0) {
            out[0] = (float)(lk / (double)(present > 0 ? present : 1));
            g_done = 0;
        }
    }
}

// ---------------------------------------------------------------------------
extern "C" void kernel_launch(void* const* d_in, const int* in_sizes, int n_in,
                              void* d_out, int out_size)
{
    const float* X   = (const float*)d_in[0];
    const int*   y   = (const int*)d_in[1];   // int32 (JAX x64 disabled)
    float*       out = (float*)d_out;

    const int total = in_sizes[0];          // N * C * T
    const int N     = in_sizes[1];          // 8192
    const int D     = total / N;            // 6144

    wcss_scatter<<<(N + 1023) / 1024, 1024>>>(y, N);

    {
        int chunks = (D + CPB - 1) / CPB;       // 24
        int segs   = (SLOT + SEGR - 1) / SEGR;  // 16
        dim3 grid(chunks, KMAX, segs);
        wcss_main<<<grid, TPB>>>(X, D);
    }

    {
        int chunks = (D + CPB - 1) / CPB;       // 24
        dim3 grid(chunks, KMAX);
        wcss_m2fin<<<grid, TPB>>>(D, chunks * KMAX, out);
    }
}